// round 2
// baseline (speedup 1.0000x reference)
#include <cuda_runtime.h>
#include <cuda_bf16.h>

#define BB 2
#define NC 128
#define NS 2048
#define NZ 256
#define NX 256
#define KK 4
#define MM (NZ * NX)

#define THREADS 256
#define NBINS 32768            // 15-bit Morton: 5 bits per dimension (32^3 cells)

// Scratch (no allocations allowed) — device globals.
__device__ int d_hist[BB * NBINS];
__device__ int d_perm[BB * MM];

__device__ __forceinline__ unsigned expand5(unsigned v) {
    // spread 5 bits to every 3rd position: b_i -> bit 3*i
    unsigned r = 0;
    #pragma unroll
    for (int i = 0; i < 5; ++i) r |= ((v >> i) & 1u) << (3 * i);
    return r;
}

__device__ __forceinline__ int morton_bin(float x, float y, float z) {
    // coords ~ [0, 0.04); quantize to 32 cells per dim (clamped for safety)
    const float s = 32.0f / 0.04f;
    int qx = min(max(__float2int_rd(x * s), 0), 31);
    int qy = min(max(__float2int_rd(y * s), 0), 31);
    int qz = min(max(__float2int_rd(z * s), 0), 31);
    return (int)(expand5(qx) | (expand5(qy) << 1) | (expand5(qz) << 2));
}

__global__ void zero_hist_kernel() {
    int i = blockIdx.x * blockDim.x + threadIdx.x;
    if (i < BB * NBINS) d_hist[i] = 0;
}

__global__ void hist_kernel(const float* __restrict__ g) {
    int t = blockIdx.x * blockDim.x + threadIdx.x;   // 0 .. BB*MM-1
    if (t >= BB * MM) return;
    int b = t / MM;
    const float* gp = g + (size_t)t * 3;
    int bin = morton_bin(gp[0], gp[1], gp[2]);
    atomicAdd(&d_hist[b * NBINS + bin], 1);
}

__global__ void scan_kernel() {
    // one block per batch; 1024 threads x 32 bins each; exclusive scan
    const int b = blockIdx.x;
    const int t = threadIdx.x;
    int* h = d_hist + b * NBINS;
    const int base = t * 32;
    int local[32];
    int sum = 0;
    #pragma unroll
    for (int i = 0; i < 32; ++i) { local[i] = h[base + i]; sum += local[i]; }

    __shared__ int s[1024];
    s[t] = sum;
    __syncthreads();
    #pragma unroll
    for (int off = 1; off < 1024; off <<= 1) {
        int v = s[t];
        int add = (t >= off) ? s[t - off] : 0;
        __syncthreads();
        s[t] = v + add;
        __syncthreads();
    }
    int excl = (t == 0) ? 0 : s[t - 1];
    #pragma unroll
    for (int i = 0; i < 32; ++i) { int c = local[i]; h[base + i] = excl; excl += c; }
}

__global__ void scatter_kernel(const float* __restrict__ g) {
    int t = blockIdx.x * blockDim.x + threadIdx.x;
    if (t >= BB * MM) return;
    int b = t / MM;
    int m = t - b * MM;
    const float* gp = g + (size_t)t * 3;
    int bin = morton_bin(gp[0], gp[1], gp[2]);
    int pos = atomicAdd(&d_hist[b * NBINS + bin], 1);
    d_perm[b * MM + pos] = m;
}

__global__ __launch_bounds__(THREADS) void das_kernel(
    const float* __restrict__ rf,   // [B, NC, NS, K]
    const float* __restrict__ g,    // [B, NZ, NX, 3]
    const float* __restrict__ pr,   // [B, NC, 3]
    const float* __restrict__ p,    // [B, 4]
    float* __restrict__ out)        // [B, NZ, NX, K]
{
    __shared__ float4 s_pr[NC];
    __shared__ float s_scale, s_base;

    const int b = blockIdx.y;
    const int t = blockIdx.x * THREADS + threadIdx.x;  // sorted-order slot
    const int m = d_perm[b * MM + t];                  // actual pixel index

    if (threadIdx.x < NC) {
        const float* q = pr + ((size_t)b * NC + threadIdx.x) * 3;
        s_pr[threadIdx.x] = make_float4(q[0], q[1], q[2], 0.0f);
    }
    if (threadIdx.x == 0) {
        const float c0 = p[b * 4 + 0];
        const float fs = p[b * 4 + 1];
        const float t0 = p[b * 4 + 2];
        s_scale = fs / c0;
        s_base  = fs * t0 / c0;
    }
    __syncthreads();

    const float* gp = g + ((size_t)b * MM + m) * 3;
    const float gx = gp[0];
    const float gy = gp[1];
    const float gz = gp[2];

    const float scale = s_scale;
    const float base  = s_base;

    const float4* __restrict__ rf4 = (const float4*)rf + (size_t)b * NC * NS;

    float ax = 0.0f, ay = 0.0f, az = 0.0f, aw = 0.0f;

    #pragma unroll 4
    for (int c = 0; c < NC; ++c) {
        const float4 pc = s_pr[c];
        const float dx = gx - pc.x;
        const float dy = gy - pc.y;
        const float dz = gz - pc.z;
        const float r2 = fmaf(dx, dx, fmaf(dy, dy, dz * dz));
        float drx;
        asm("sqrt.approx.f32 %0, %1;" : "=f"(drx) : "f"(r2));

        float s = fmaf(scale, drx + gz, base);
        s = fminf(fmaxf(s, 0.0f), (float)(NS - 1));
        const float i0f = fminf(floorf(s), (float)(NS - 2));
        const int   i0  = (int)i0f;
        const float w   = s - i0f;
        const float wm  = 1.0f - w;

        const float4* ptr = rf4 + (size_t)c * NS + i0;
        const float4 y0 = ptr[0];
        const float4 y1 = ptr[1];

        ax = fmaf(wm, y0.x, fmaf(w, y1.x, ax));
        ay = fmaf(wm, y0.y, fmaf(w, y1.y, ay));
        az = fmaf(wm, y0.z, fmaf(w, y1.z, az));
        aw = fmaf(wm, y0.w, fmaf(w, y1.w, aw));
    }

    ((float4*)out)[(size_t)b * MM + m] = make_float4(ax, ay, az, aw);
}

extern "C" void kernel_launch(void* const* d_in, const int* in_sizes, int n_in,
                              void* d_out, int out_size) {
    const float* rf = (const float*)d_in[0];
    const float* g  = (const float*)d_in[1];
    const float* pr = (const float*)d_in[2];
    const float* p  = (const float*)d_in[3];
    float* out = (float*)d_out;

    zero_hist_kernel<<<(BB * NBINS + 255) / 256, 256>>>();
    hist_kernel<<<(BB * MM + 255) / 256, 256>>>(g);
    scan_kernel<<<BB, 1024>>>();
    scatter_kernel<<<(BB * MM + 255) / 256, 256>>>(g);

    dim3 grid(MM / THREADS, BB);
    das_kernel<<<grid, THREADS>>>(rf, g, pr, p, out);
}

// round 4
// speedup vs baseline: 1.0381x; 1.0381x over previous
#include <cuda_runtime.h>
#include <cuda_bf16.h>

#define BB 2
#define NC 128
#define NS 2048
#define NZ 256
#define NX 256
#define KK 4
#define MM (NZ * NX)

#define THREADS 256
#define PXPT 2                      // pixels per thread in das kernel

// Pair-packed rf: rfp[(b*NC+c)*NS + s] = {rf[s,0:4], rf[s+1,0:4]}  (32B per s)
__device__ float4 d_rfp[BB * NC * NS * 2];

__global__ void pack_kernel(const float* __restrict__ rf) {
    const int t = blockIdx.x * blockDim.x + threadIdx.x;   // 0 .. BB*NC*NS-1
    if (t >= BB * NC * NS) return;
    const int s = t & (NS - 1);
    const float4* rf4 = (const float4*)rf;
    const float4 y0 = rf4[t];
    const float4 y1 = rf4[t + (s < NS - 1 ? 1 : 0)];
    d_rfp[2 * t + 0] = y0;
    d_rfp[2 * t + 1] = y1;
}

__global__ __launch_bounds__(THREADS) void das_kernel(
    const float* __restrict__ g,    // [B, NZ, NX, 3]
    const float* __restrict__ pr,   // [B, NC, 3]
    const float* __restrict__ p,    // [B, 4]
    float* __restrict__ out)        // [B, NZ, NX, K]
{
    __shared__ float4 s_pr[NC];
    __shared__ float s_scale, s_base;

    const int b = blockIdx.y;
    const int m0 = blockIdx.x * (THREADS * PXPT) + threadIdx.x;
    const int m1 = m0 + THREADS;

    if (threadIdx.x < NC) {
        const float* q = pr + ((size_t)b * NC + threadIdx.x) * 3;
        s_pr[threadIdx.x] = make_float4(q[0], q[1], q[2], 0.0f);
    }
    if (threadIdx.x == 0) {
        const float c0 = p[b * 4 + 0];
        const float fs = p[b * 4 + 1];
        const float t0 = p[b * 4 + 2];
        s_scale = fs / c0;
        s_base  = fs * t0 / c0;
    }
    __syncthreads();

    const float* gp0 = g + ((size_t)b * MM + m0) * 3;
    const float* gp1 = g + ((size_t)b * MM + m1) * 3;
    const float gx0 = gp0[0], gy0 = gp0[1], gz0 = gp0[2];
    const float gx1 = gp1[0], gy1 = gp1[1], gz1 = gp1[2];

    const float scale = s_scale;
    const float base  = s_base;

    const float4* __restrict__ rfp = d_rfp + (size_t)b * NC * NS * 2;

    float4 a0 = make_float4(0.f, 0.f, 0.f, 0.f);
    float4 a1 = make_float4(0.f, 0.f, 0.f, 0.f);

    #pragma unroll 4
    for (int c = 0; c < NC; ++c) {
        const float4 pc = s_pr[c];
        const size_t rowoff = (size_t)c * (NS * 2);

        // pixel 0
        {
            const float dx = gx0 - pc.x, dy = gy0 - pc.y, dz = gz0 - pc.z;
            const float r2 = fmaf(dx, dx, fmaf(dy, dy, dz * dz));
            float drx; asm("sqrt.approx.f32 %0, %1;" : "=f"(drx) : "f"(r2));
            float s = fmaf(scale, drx + gz0, base);
            s = fminf(fmaxf(s, 0.0f), (float)(NS - 1));
            const float i0f = fminf(floorf(s), (float)(NS - 2));
            const int   i0  = (int)i0f;
            const float w  = s - i0f;
            const float wm = 1.0f - w;
            const float4* ptr = rfp + rowoff + 2 * i0;   // 32B-aligned pair
            const float4 y0 = ptr[0];
            const float4 y1 = ptr[1];
            a0.x = fmaf(wm, y0.x, fmaf(w, y1.x, a0.x));
            a0.y = fmaf(wm, y0.y, fmaf(w, y1.y, a0.y));
            a0.z = fmaf(wm, y0.z, fmaf(w, y1.z, a0.z));
            a0.w = fmaf(wm, y0.w, fmaf(w, y1.w, a0.w));
        }
        // pixel 1
        {
            const float dx = gx1 - pc.x, dy = gy1 - pc.y, dz = gz1 - pc.z;
            const float r2 = fmaf(dx, dx, fmaf(dy, dy, dz * dz));
            float drx; asm("sqrt.approx.f32 %0, %1;" : "=f"(drx) : "f"(r2));
            float s = fmaf(scale, drx + gz1, base);
            s = fminf(fmaxf(s, 0.0f), (float)(NS - 1));
            const float i0f = fminf(floorf(s), (float)(NS - 2));
            const int   i0  = (int)i0f;
            const float w  = s - i0f;
            const float wm = 1.0f - w;
            const float4* ptr = rfp + rowoff + 2 * i0;
            const float4 y0 = ptr[0];
            const float4 y1 = ptr[1];
            a1.x = fmaf(wm, y0.x, fmaf(w, y1.x, a1.x));
            a1.y = fmaf(wm, y0.y, fmaf(w, y1.y, a1.y));
            a1.z = fmaf(wm, y0.z, fmaf(w, y1.z, a1.z));
            a1.w = fmaf(wm, y0.w, fmaf(w, y1.w, a1.w));
        }
    }

    float4* o = (float4*)out + (size_t)b * MM;
    o[m0] = a0;
    o[m1] = a1;
}

extern "C" void kernel_launch(void* const* d_in, const int* in_sizes, int n_in,
                              void* d_out, int out_size) {
    const float* rf = (const float*)d_in[0];
    const float* g  = (const float*)d_in[1];
    const float* pr = (const float*)d_in[2];
    const float* p  = (const float*)d_in[3];
    float* out = (float*)d_out;

    pack_kernel<<<(BB * NC * NS + 255) / 256, 256>>>(rf);

    dim3 grid(MM / (THREADS * PXPT), BB);
    das_kernel<<<grid, THREADS>>>(g, pr, p, out);
}

// round 6
// speedup vs baseline: 1.2018x; 1.1577x over previous
#include <cuda_runtime.h>
#include <cuda_fp16.h>
#include <cuda_bf16.h>

#define BB 2
#define NC 128
#define NS 2048
#define NZ 256
#define NX 256
#define KK 4
#define MM (NZ * NX)

#define THREADS 256

// fp16 pair-packed rf: entry (b,c,s) = 8 halves {rf[s,0:4], rf[s+1,0:4]} = 16B
__device__ uint4 d_rfp[BB * NC * NS];

__global__ void pack_kernel(const float* __restrict__ rf) {
    const int t = blockIdx.x * blockDim.x + threadIdx.x;   // 0 .. BB*NC*NS-1
    if (t >= BB * NC * NS) return;
    const int s = t & (NS - 1);
    const float4* rf4 = (const float4*)rf;
    const float4 y0 = rf4[t];
    const float4 y1 = rf4[t + (s < NS - 1 ? 1 : 0)];
    __half2 h0 = __floats2half2_rn(y0.x, y0.y);
    __half2 h1 = __floats2half2_rn(y0.z, y0.w);
    __half2 h2 = __floats2half2_rn(y1.x, y1.y);
    __half2 h3 = __floats2half2_rn(y1.z, y1.w);
    uint4 v;
    v.x = *(unsigned*)&h0;
    v.y = *(unsigned*)&h1;
    v.z = *(unsigned*)&h2;
    v.w = *(unsigned*)&h3;
    d_rfp[t] = v;
}

__global__ __launch_bounds__(THREADS) void das_kernel(
    const float* __restrict__ g,    // [B, NZ, NX, 3]
    const float* __restrict__ pr,   // [B, NC, 3]
    const float* __restrict__ p,    // [B, 4]
    float* __restrict__ out)        // [B, NZ, NX, K]
{
    __shared__ float4 s_pr[NC];
    __shared__ float s_scale, s_base;

    const int b = blockIdx.y;
    const int m = blockIdx.x * THREADS + threadIdx.x;

    if (threadIdx.x < NC) {
        const float* q = pr + ((size_t)b * NC + threadIdx.x) * 3;
        s_pr[threadIdx.x] = make_float4(q[0], q[1], q[2], 0.0f);
    }
    if (threadIdx.x == 0) {
        const float c0 = p[b * 4 + 0];
        const float fs = p[b * 4 + 1];
        const float t0 = p[b * 4 + 2];
        s_scale = fs / c0;
        s_base  = fs * t0 / c0;
    }
    __syncthreads();

    const float* gp = g + ((size_t)b * MM + m) * 3;
    const float gx = gp[0];
    const float gy = gp[1];
    const float gz = gp[2];

    const float scale = s_scale;
    const float base  = s_base;

    const uint4* __restrict__ rfp = d_rfp + (size_t)b * NC * NS;

    float ax = 0.0f, ay = 0.0f, az = 0.0f, aw = 0.0f;

    #pragma unroll 4
    for (int c = 0; c < NC; ++c) {
        const float4 pc = s_pr[c];
        const float dx = gx - pc.x;
        const float dy = gy - pc.y;
        const float dz = gz - pc.z;
        const float r2 = fmaf(dx, dx, fmaf(dy, dy, dz * dz));
        float drx;
        asm("sqrt.approx.f32 %0, %1;" : "=f"(drx) : "f"(r2));

        float s = fmaf(scale, drx + gz, base);
        s = fminf(fmaxf(s, 0.0f), (float)(NS - 1));
        const float i0f = fminf(floorf(s), (float)(NS - 2));
        const int   i0  = (int)i0f;
        const float w   = s - i0f;
        const float wm  = 1.0f - w;

        const uint4 v = rfp[(size_t)c * NS + i0];   // ONE 16B gather, one sector

        const float2 f0 = __half22float2(*(const __half2*)&v.x);  // y0.x, y0.y
        const float2 f1 = __half22float2(*(const __half2*)&v.y);  // y0.z, y0.w
        const float2 f2 = __half22float2(*(const __half2*)&v.z);  // y1.x, y1.y
        const float2 f3 = __half22float2(*(const __half2*)&v.w);  // y1.z, y1.w

        ax = fmaf(wm, f0.x, fmaf(w, f2.x, ax));
        ay = fmaf(wm, f0.y, fmaf(w, f2.y, ay));
        az = fmaf(wm, f1.x, fmaf(w, f3.x, az));
        aw = fmaf(wm, f1.y, fmaf(w, f3.y, aw));
    }

    ((float4*)out)[(size_t)b * MM + m] = make_float4(ax, ay, az, aw);
}

extern "C" void kernel_launch(void* const* d_in, const int* in_sizes, int n_in,
                              void* d_out, int out_size) {
    const float* rf = (const float*)d_in[0];
    const float* g  = (const float*)d_in[1];
    const float* pr = (const float*)d_in[2];
    const float* p  = (const float*)d_in[3];
    float* out = (float*)d_out;

    pack_kernel<<<(BB * NC * NS + 255) / 256, 256>>>(rf);

    dim3 grid(MM / THREADS, BB);
    das_kernel<<<grid, THREADS>>>(g, pr, p, out);
}

// round 7
// speedup vs baseline: 1.7171x; 1.4288x over previous
#include <cuda_runtime.h>
#include <cuda_fp16.h>
#include <cuda_bf16.h>

#define BB 2
#define NC 128
#define NS 2048
#define NZ 256
#define NX 256
#define KK 4
#define MM (NZ * NX)

#define DTHREADS 1024                 // das block size; block owns 1024 pixels
#define NS4 (NS / 2)                  // uint4 (=2 samples) per channel row: 1024

// fp16 rf: sample s of channel row = 4 halves (8B). Stored as uint4 pairs of
// samples for coalesced staging: d_rf16[(b*NC+c)*NS4 + i] covers samples 2i,2i+1.
__device__ uint4 d_rf16[BB * NC * NS4];

__global__ void pack_kernel(const float* __restrict__ rf) {
    const int t = blockIdx.x * blockDim.x + threadIdx.x;   // 0 .. BB*NC*NS4-1
    if (t >= BB * NC * NS4) return;
    const int row = t >> 10;            // channel-row index (b*NC+c)
    const int pos = t & (NS4 - 1);      // uint4 position within row
    const float4* rf4 = (const float4*)rf + (size_t)row * NS;
    const float4 y0 = rf4[2 * pos + 0];
    const float4 y1 = rf4[2 * pos + 1];
    __half2 h0 = __floats2half2_rn(y0.x, y0.y);
    __half2 h1 = __floats2half2_rn(y0.z, y0.w);
    __half2 h2 = __floats2half2_rn(y1.x, y1.y);
    __half2 h3 = __floats2half2_rn(y1.z, y1.w);
    uint4 v;
    v.x = *(unsigned*)&h0;
    v.y = *(unsigned*)&h1;
    v.z = *(unsigned*)&h2;
    v.w = *(unsigned*)&h3;
    d_rf16[t] = v;
}

__global__ __launch_bounds__(DTHREADS) void das_kernel(
    const float* __restrict__ g,    // [B, NZ, NX, 3]
    const float* __restrict__ pr,   // [B, NC, 3]
    const float* __restrict__ p,    // [B, 4]
    float* __restrict__ out)        // [B, NZ, NX, K]
{
    __shared__ uint4 buf[2][NS4];   // double-buffered channel row: 2 x 16KB
    __shared__ float4 s_pr[NC];
    __shared__ float s_scale, s_base;

    const int tid = threadIdx.x;
    const int b = blockIdx.x >> 6;                    // 64 blocks per batch
    const int m = ((blockIdx.x & 63) << 10) + tid;    // pixel index

    if (tid < NC) {
        const float* q = pr + ((size_t)b * NC + tid) * 3;
        s_pr[tid] = make_float4(q[0], q[1], q[2], 0.0f);
    }
    if (tid == 0) {
        const float c0 = p[b * 4 + 0];
        const float fs = p[b * 4 + 1];
        const float t0 = p[b * 4 + 2];
        s_scale = fs / c0;
        s_base  = fs * t0 / c0;
    }

    const float* gp = g + ((size_t)b * MM + m) * 3;
    const float gx = gp[0];
    const float gy = gp[1];
    const float gz = gp[2];

    const uint4* __restrict__ rfg = d_rf16 + (size_t)b * NC * NS4;

    // preload channel 0
    uint4 nxt = rfg[tid];
    buf[0][tid] = nxt;
    __syncthreads();   // pr/params + buf0 visible

    const float scale = s_scale;
    const float base  = s_base;

    float ax = 0.0f, ay = 0.0f, az = 0.0f, aw = 0.0f;

    for (int c = 0; c < NC; ++c) {
        // prefetch next channel row (non-blocking; consumed after sync B)
        if (c + 1 < NC) nxt = rfg[(c + 1) * NS4 + tid];

        // --- compute channel c from buf[c&1] ---
        const float4 pc = s_pr[c];
        const float dx = gx - pc.x;
        const float dy = gy - pc.y;
        const float dz = gz - pc.z;
        const float r2 = fmaf(dx, dx, fmaf(dy, dy, dz * dz));
        float drx;
        asm("sqrt.approx.f32 %0, %1;" : "=f"(drx) : "f"(r2));

        float s = fmaf(scale, drx + gz, base);
        s = fminf(fmaxf(s, 0.0f), (float)(NS - 1));
        const float i0f = fminf(floorf(s), (float)(NS - 2));
        const int   i0  = (int)i0f;
        const float w   = s - i0f;
        const float wm  = 1.0f - w;

        const uint2* row = (const uint2*)buf[c & 1];  // 8B per sample
        const uint2 t0v = row[i0];        // tap 0: 4 halves
        const uint2 t1v = row[i0 + 1];    // tap 1: 4 halves

        const float2 f0 = __half22float2(*(const __half2*)&t0v.x);
        const float2 f1 = __half22float2(*(const __half2*)&t0v.y);
        const float2 f2 = __half22float2(*(const __half2*)&t1v.x);
        const float2 f3 = __half22float2(*(const __half2*)&t1v.y);

        ax = fmaf(wm, f0.x, fmaf(w, f2.x, ax));
        ay = fmaf(wm, f0.y, fmaf(w, f2.y, ay));
        az = fmaf(wm, f1.x, fmaf(w, f3.x, az));
        aw = fmaf(wm, f1.y, fmaf(w, f3.y, aw));

        __syncthreads();   // all reads of buf[(c+1)&1] (from iter c-1) done
        if (c + 1 < NC) buf[(c + 1) & 1][tid] = nxt;
        __syncthreads();   // next buffer visible for iter c+1
    }

    ((float4*)out)[(size_t)b * MM + m] = make_float4(ax, ay, az, aw);
}

extern "C" void kernel_launch(void* const* d_in, const int* in_sizes, int n_in,
                              void* d_out, int out_size) {
    const float* rf = (const float*)d_in[0];
    const float* g  = (const float*)d_in[1];
    const float* pr = (const float*)d_in[2];
    const float* p  = (const float*)d_in[3];
    float* out = (float*)d_out;

    pack_kernel<<<(BB * NC * NS4 + 255) / 256, 256>>>(rf);

    das_kernel<<<BB * 64, DTHREADS>>>(g, pr, p, out);
}